// round 13
// baseline (speedup 1.0000x reference)
#include <cuda_runtime.h>
#include <cuda_bf16.h>
#include <math.h>

#define BINS 30
#define P1T 128
#define MAX_ROWS 8192

// Global scratch: per-(bin,row) BCE sums (bin-major) + global bin counts.
// g_cnt is zero at module load; zero_cnt_kernel re-zeroes it at the END of
// each call so every graph replay starts from zero.
__device__ float        g_S[BINS * MAX_ROWS];
__device__ unsigned int g_cnt[BINS];

__global__ void zero_cnt_kernel() {
    if (threadIdx.x < BINS) g_cnt[threadIdx.x] = 0u;
}

// ---------------------------------------------------------------------------
// Hybrid fast/exact binning.
// Fast path (4 transcendental-ish instrs): s~ = RCP(1 + EX2(-x*log2e)).
//   |s~ - s_exact| <= ~4e-7  ->  <= 1.2e-5 bin units.
// If the fast bin position is within DELTA=1e-3 of a bin edge (83x margin),
// recompute with the PROVEN exact sequence (expf + IEEE div) so the final bin
// is bit-identical to the rel_err=6.2e-6 kernel. ~0.2% of elements take it.
// BCE value: (t?0:x) + __logf(w1_fast) — value-only fast log (proven safe).
// ---------------------------------------------------------------------------
struct BinVal { int slot; float bce; };

__device__ __forceinline__ BinVal elem_math(float xv, int ti, int tid) {
    const float DELTA = 1e-3f;

    float e  = __expf(-xv);              // FMUL + MUFU.EX2
    float w1 = 1.0f + e;
    float s  = __fdividef(1.0f, w1);     // MUFU.RCP
    float g  = ti ? (1.0f - s) : s;
    float gb = g * 29.9999f;
    int   b  = (int)gb;                  // g>=-4e-7 -> trunc == floor here
    float fr = gb - (float)b;

    if (fr < DELTA || fr > 1.0f - DELTA) {
        // exact recompute (matches reference fp32 rounding sequence)
        float ea  = expf(-xv);
        float w1a = 1.0f + ea;
        float sa  = 1.0f / w1a;          // IEEE division
        float ga  = ti ? (1.0f - sa) : sa;
        b = (int)(ga * 29.9999f);
    }
    b = b < 0 ? 0 : (b > (BINS - 1) ? (BINS - 1) : b);

    BinVal r;
    r.slot = b * P1T + tid;
    r.bce  = (ti ? 0.0f : xv) + __logf(w1);
    return r;
}

__device__ __forceinline__ void rmw8(float2* s_h, const BinVal* r) {
    #pragma unroll
    for (int k = 0; k < 8; k++) {
        float2 v = s_h[r[k].slot];
        v.x += r[k].bce;
        v.y += 1.0f;
        s_h[r[k].slot] = v;
    }
}

// ---------------------------------------------------------------------------
// Pass 1: one block per row, single read of logits+target.
// 2-deep software pipeline (batch i+1's vec4 loads before batch i's math),
// 8-wide independent math chains, fused (sum,count) float2 smem slots
// (slot = b*128+tid -> 64-bit phase-split conflict-free).
// ---------------------------------------------------------------------------
__global__ void __launch_bounds__(P1T)
pass1_kernel(const float4* __restrict__ logits,
             const int4*  __restrict__ target,
             int rows, int c4)
{
    __shared__ float2 s_h[BINS * P1T];    // 30720 B

    const int tid = threadIdx.x;

    #pragma unroll
    for (int b = 0; b < BINS; b++)
        s_h[b * P1T + tid] = make_float2(0.0f, 0.0f);
    // own column only -> no sync needed before hot loop

    const int row = blockIdx.x;
    const float4* lrow = logits + (size_t)row * c4;
    const int4*   trow = target + (size_t)row * c4;

    // c4 = 2048, P1T = 128 -> exactly 16 float4 steps/thread = 8 dual-batches.
    int i = tid;

    if (i + P1T < c4) {
        float4 x0 = lrow[i];
        float4 x1 = lrow[i + P1T];
        int4   t0 = trow[i];
        int4   t1 = trow[i + P1T];

        for (;;) {
            const int inext = i + 2 * P1T;
            const bool more = (inext + P1T < c4);

            float4 xn0, xn1; int4 tn0, tn1;
            if (more) {                       // prefetch next batch first
                xn0 = lrow[inext];
                xn1 = lrow[inext + P1T];
                tn0 = trow[inext];
                tn1 = trow[inext + P1T];
            }

            BinVal r[8];
            r[0] = elem_math(x0.x, t0.x, tid);
            r[1] = elem_math(x0.y, t0.y, tid);
            r[2] = elem_math(x0.z, t0.z, tid);
            r[3] = elem_math(x0.w, t0.w, tid);
            r[4] = elem_math(x1.x, t1.x, tid);
            r[5] = elem_math(x1.y, t1.y, tid);
            r[6] = elem_math(x1.z, t1.z, tid);
            r[7] = elem_math(x1.w, t1.w, tid);
            rmw8(s_h, r);

            if (!more) { i = inext; break; }
            x0 = xn0; x1 = xn1; t0 = tn0; t1 = tn1;
            i = inext;
        }
    }
    // remainder (not taken for 8192 cols, kept for generality)
    for (; i < c4; i += P1T) {
        float4 x = lrow[i];
        int4   t = trow[i];
        BinVal r[4];
        r[0] = elem_math(x.x, t.x, tid);
        r[1] = elem_math(x.y, t.y, tid);
        r[2] = elem_math(x.z, t.z, tid);
        r[3] = elem_math(x.w, t.w, tid);
        #pragma unroll
        for (int k = 0; k < 4; k++) {
            float2 v = s_h[r[k].slot];
            v.x += r[k].bce;
            v.y += 1.0f;
            s_h[r[k].slot] = v;
        }
    }
    __syncthreads();

    // Cross-thread reduce: warp w handles bins w, w+4, ...
    int warp = tid >> 5, lane = tid & 31;
    for (int b = warp; b < BINS; b += 4) {
        float fs = 0.0f, fc = 0.0f;
        #pragma unroll
        for (int k = 0; k < 4; k++) {
            float2 v = s_h[b * P1T + k * 32 + lane];
            fs += v.x;
            fc += v.y;
        }
        #pragma unroll
        for (int off = 16; off > 0; off >>= 1) {
            fs += __shfl_down_sync(0xffffffff, fs, off);
            fc += __shfl_down_sync(0xffffffff, fc, off);
        }
        if (lane == 0) {
            g_S[b * rows + row] = fs;
            unsigned int c = (unsigned int)fc;
            if (c) atomicAdd(&g_cnt[b], c);
        }
    }
}

// ---------------------------------------------------------------------------
// Finalize: beta from counts; out[row] = (1/cols) * dot(beta, S[:,row]).
// ---------------------------------------------------------------------------
__global__ void __launch_bounds__(256)
finalize_kernel(float* __restrict__ out, int rows, float inv_cols, float tot)
{
    __shared__ float beta[BINS];
    if (threadIdx.x < 32) {
        unsigned int c = (threadIdx.x < BINS) ? g_cnt[threadIdx.x] : 0u;
        unsigned int nz = __ballot_sync(0xffffffff, c > 0u);
        float nonempty = (float)__popc(nz);
        if (threadIdx.x < BINS)
            beta[threadIdx.x] = tot / fmaxf((float)c * nonempty, 1e-4f);
    }
    __syncthreads();

    int row = blockIdx.x * blockDim.x + threadIdx.x;
    if (row < rows) {
        float acc = 0.0f;
        #pragma unroll
        for (int b = 0; b < BINS; b++)
            acc += beta[b] * g_S[b * rows + row];
        out[row] = acc * inv_cols;
    }
}

// ---------------------------------------------------------------------------
extern "C" void kernel_launch(void* const* d_in, const int* in_sizes, int n_in,
                              void* d_out, int out_size)
{
    const float* logits = (const float*)d_in[0];
    const int*   target = (const int*)d_in[1];
    float*       out    = (float*)d_out;

    int n    = in_sizes[0];          // 33554432
    int rows = out_size;             // 4096
    int cols = n / rows;             // 8192
    int c4   = cols >> 2;

    // pass1 first: ncu's captured launch index (≡0 mod 3) lands on pass1.
    pass1_kernel<<<rows, P1T>>>(
        (const float4*)logits, (const int4*)target, rows, c4);
    finalize_kernel<<<(rows + 255) / 256, 256>>>(
        out, rows, 1.0f / (float)cols, (float)n);
    zero_cnt_kernel<<<1, 32>>>();
}

// round 14
// speedup vs baseline: 1.0904x; 1.0904x over previous
#include <cuda_runtime.h>
#include <cuda_bf16.h>
#include <math.h>

#define BINS 30
#define P1T 128
#define MAX_ROWS 8192

// Global scratch: per-(bin,row) BCE sums (bin-major) + global bin counts.
// g_cnt is zero at module load; zero_cnt_kernel re-zeroes it at the END of
// each call so every graph replay starts from zero.
__device__ float        g_S[BINS * MAX_ROWS];
__device__ unsigned int g_cnt[BINS];

__global__ void zero_cnt_kernel() {
    if (threadIdx.x < BINS) g_cnt[threadIdx.x] = 0u;
}

// ---------------------------------------------------------------------------
// Hybrid fast/exact binning (validated at rel_err 6.2e-6 in R13):
// fast sigmoid via EX2/RCP; if the bin position is within 1e-3 of an edge,
// recompute with the exact reference sequence (expf + IEEE div).
// ---------------------------------------------------------------------------
struct BinVal { int slot; float bce; };

__device__ __forceinline__ BinVal elem_math(float xv, int ti, int tid) {
    const float DELTA = 1e-3f;

    float e  = __expf(-xv);              // FMUL + MUFU.EX2
    float w1 = 1.0f + e;
    float s  = __fdividef(1.0f, w1);     // MUFU.RCP
    float g  = ti ? (1.0f - s) : s;
    float gb = g * 29.9999f;
    int   b  = (int)gb;
    float fr = gb - (float)b;

    if (fr < DELTA || fr > 1.0f - DELTA) {
        float ea  = expf(-xv);
        float w1a = 1.0f + ea;
        float sa  = 1.0f / w1a;          // IEEE division
        float ga  = ti ? (1.0f - sa) : sa;
        b = (int)(ga * 29.9999f);
    }
    b = b < 0 ? 0 : (b > (BINS - 1) ? (BINS - 1) : b);

    BinVal r;
    r.slot = b * P1T + tid;
    r.bce  = (ti ? 0.0f : xv) + __logf(w1);
    return r;
}

// Packed per-thread bin counters: 4 x u64, 8 bins per word, 8 bits per bin.
// Max 64 elems/thread -> no byte overflow. Pure ALU, no memory chain.
struct PackCnt {
    unsigned long long c0, c1, c2, c3;
    __device__ __forceinline__ void add(int b) {
        unsigned long long inc = 1ull << ((b & 7) << 3);
        int w = b >> 3;
        if      (w == 0) c0 += inc;
        else if (w == 1) c1 += inc;
        else if (w == 2) c2 += inc;
        else             c3 += inc;
    }
    __device__ __forceinline__ unsigned int get(int b) const {
        unsigned long long w = (b < 8) ? c0 : (b < 16) ? c1 : (b < 24) ? c2 : c3;
        return (unsigned int)((w >> ((b & 7) << 3)) & 0xFFull);
    }
};

__device__ __forceinline__ void rmw4(float* hist, const BinVal* r) {
    #pragma unroll
    for (int k = 0; k < 4; k++)
        hist[r[k].slot] += r[k].bce;
}

// ---------------------------------------------------------------------------
// Pass 1: one block per row, single read of logits+target.
// Serial-chain fix: TWO float histograms (s_a for batch-half 0, s_b for
// half 1) -> two independent 4-link LDS/FADD/STS chains per batch instead of
// one 8-link float2 chain; counts in packed registers (no smem RMW at all).
// ---------------------------------------------------------------------------
__global__ void __launch_bounds__(P1T)
pass1_kernel(const float4* __restrict__ logits,
             const int4*  __restrict__ target,
             int rows, int c4)
{
    __shared__ float        s_a[BINS * P1T];   // 15360 B
    __shared__ float        s_b[BINS * P1T];   // 15360 B
    __shared__ unsigned int s_wcnt[4 * BINS];  // per-warp unpacked counts

    const int tid = threadIdx.x;

    #pragma unroll
    for (int b = 0; b < BINS; b++) {
        s_a[b * P1T + tid] = 0.0f;
        s_b[b * P1T + tid] = 0.0f;
    }
    // own columns only -> no sync needed before hot loop

    PackCnt pc = {0ull, 0ull, 0ull, 0ull};

    const int row = blockIdx.x;
    const float4* lrow = logits + (size_t)row * c4;
    const int4*   trow = target + (size_t)row * c4;

    // c4 = 2048, P1T = 128 -> exactly 16 float4 steps/thread = 8 dual-batches.
    int i = tid;

    if (i + P1T < c4) {
        float4 x0 = lrow[i];
        float4 x1 = lrow[i + P1T];
        int4   t0 = trow[i];
        int4   t1 = trow[i + P1T];

        for (;;) {
            const int inext = i + 2 * P1T;
            const bool more = (inext + P1T < c4);

            float4 xn0, xn1; int4 tn0, tn1;
            if (more) {                       // prefetch next batch first
                xn0 = lrow[inext];
                xn1 = lrow[inext + P1T];
                tn0 = trow[inext];
                tn1 = trow[inext + P1T];
            }

            BinVal ra[4], rb[4];
            ra[0] = elem_math(x0.x, t0.x, tid);
            ra[1] = elem_math(x0.y, t0.y, tid);
            ra[2] = elem_math(x0.z, t0.z, tid);
            ra[3] = elem_math(x0.w, t0.w, tid);
            rb[0] = elem_math(x1.x, t1.x, tid);
            rb[1] = elem_math(x1.y, t1.y, tid);
            rb[2] = elem_math(x1.z, t1.z, tid);
            rb[3] = elem_math(x1.w, t1.w, tid);

            rmw4(s_a, ra);                    // chain A (4 links)
            rmw4(s_b, rb);                    // chain B (independent)

            #pragma unroll
            for (int k = 0; k < 4; k++) { pc.add(ra[k].slot / P1T); }
            #pragma unroll
            for (int k = 0; k < 4; k++) { pc.add(rb[k].slot / P1T); }

            if (!more) { i = inext; break; }
            x0 = xn0; x1 = xn1; t0 = tn0; t1 = tn1;
            i = inext;
        }
    }
    // remainder (not taken for 8192 cols, kept for generality)
    for (; i < c4; i += P1T) {
        float4 x = lrow[i];
        int4   t = trow[i];
        BinVal r[4];
        r[0] = elem_math(x.x, t.x, tid);
        r[1] = elem_math(x.y, t.y, tid);
        r[2] = elem_math(x.z, t.z, tid);
        r[3] = elem_math(x.w, t.w, tid);
        rmw4(s_a, r);
        #pragma unroll
        for (int k = 0; k < 4; k++) { pc.add(r[k].slot / P1T); }
    }

    // Per-warp count reduction (register -> redux -> smem), no RMW chains.
    const int warp = tid >> 5, lane = tid & 31;
    #pragma unroll
    for (int b = 0; b < BINS; b++) {
        unsigned int v = __reduce_add_sync(0xffffffff, pc.get(b));
        if (lane == 0) s_wcnt[warp * BINS + b] = v;
    }
    __syncthreads();

    // Cross-thread reduce of bce sums: warp w handles bins w, w+4, ...
    for (int b = warp; b < BINS; b += 4) {
        float fs = 0.0f;
        #pragma unroll
        for (int k = 0; k < 4; k++) {
            int s = b * P1T + k * 32 + lane;
            fs += s_a[s] + s_b[s];
        }
        #pragma unroll
        for (int off = 16; off > 0; off >>= 1)
            fs += __shfl_down_sync(0xffffffff, fs, off);
        if (lane == 0)
            g_S[b * rows + row] = fs;
    }

    // Global count accumulation: 30 atomics per block.
    if (tid < BINS) {
        unsigned int c = s_wcnt[tid] + s_wcnt[BINS + tid] +
                         s_wcnt[2 * BINS + tid] + s_wcnt[3 * BINS + tid];
        if (c) atomicAdd(&g_cnt[tid], c);
    }
}

// ---------------------------------------------------------------------------
// Finalize: beta from counts; out[row] = (1/cols) * dot(beta, S[:,row]).
// ---------------------------------------------------------------------------
__global__ void __launch_bounds__(256)
finalize_kernel(float* __restrict__ out, int rows, float inv_cols, float tot)
{
    __shared__ float beta[BINS];
    if (threadIdx.x < 32) {
        unsigned int c = (threadIdx.x < BINS) ? g_cnt[threadIdx.x] : 0u;
        unsigned int nz = __ballot_sync(0xffffffff, c > 0u);
        float nonempty = (float)__popc(nz);
        if (threadIdx.x < BINS)
            beta[threadIdx.x] = tot / fmaxf((float)c * nonempty, 1e-4f);
    }
    __syncthreads();

    int row = blockIdx.x * blockDim.x + threadIdx.x;
    if (row < rows) {
        float acc = 0.0f;
        #pragma unroll
        for (int b = 0; b < BINS; b++)
            acc += beta[b] * g_S[b * rows + row];
        out[row] = acc * inv_cols;
    }
}

// ---------------------------------------------------------------------------
extern "C" void kernel_launch(void* const* d_in, const int* in_sizes, int n_in,
                              void* d_out, int out_size)
{
    const float* logits = (const float*)d_in[0];
    const int*   target = (const int*)d_in[1];
    float*       out    = (float*)d_out;

    int n    = in_sizes[0];          // 33554432
    int rows = out_size;             // 4096
    int cols = n / rows;             // 8192
    int c4   = cols >> 2;

    // pass1 first: ncu's captured launch index (≡0 mod 3) lands on pass1.
    pass1_kernel<<<rows, P1T>>>(
        (const float4*)logits, (const int4*)target, rows, c4);
    finalize_kernel<<<(rows + 255) / 256, 256>>>(
        out, rows, 1.0f / (float)cols, (float)n);
    zero_cnt_kernel<<<1, 32>>>();
}